// round 8
// baseline (speedup 1.0000x reference)
#include <cuda_runtime.h>
#include <cuda_bf16.h>
#include <stdint.h>

#define NN 100000
#define EE 1600000
#define FN 32
#define FE 8
#define HH 64
#define NPB 32
#define NB_SCAN 391   // ceil(NN/256)

// ---------------- scratch (device globals) ------------------------------------
__device__ float g_g[NN * HH];    // g' = (h@W) * dinv[src-side]
__device__ float g_acc[NN * HH];  // aggregated (self + in-edges)
__device__ float g_a[NN * HH];
__device__ float g_b[NN * HH];
__device__ float g_dinv[NN];
__device__ int   g_degi[NN];
__device__ int   g_off[NN];
__device__ int   g_offtmp[NN];
__device__ int   g_cur[NN];
__device__ int   g_bsum[512];
__device__ int2  g_csr[EE];       // (src, edge_id) grouped by dst

// ---------------- degree / norm / CSR build -----------------------------------
__global__ void k_zero() {
    int n = blockIdx.x * blockDim.x + threadIdx.x;
    if (n < NN) g_degi[n] = 0;
}

__global__ void k_deg(const int* __restrict__ ei) {
    int e = blockIdx.x * blockDim.x + threadIdx.x;
    if (e < EE) atomicAdd(&g_degi[__ldg(&ei[EE + e])], 1);
}

// block-level inclusive scan (Hillis-Steele), emit exclusive + block sums
__global__ void k_scanA() {
    __shared__ int sm[256];
    int t = threadIdx.x;
    int idx = blockIdx.x * 256 + t;
    int v = (idx < NN) ? g_degi[idx] : 0;
    sm[t] = v;
    __syncthreads();
#pragma unroll
    for (int o = 1; o < 256; o <<= 1) {
        int x = (t >= o) ? sm[t - o] : 0;
        __syncthreads();
        sm[t] += x;
        __syncthreads();
    }
    if (idx < NN) g_offtmp[idx] = sm[t] - v;
    if (t == 255) g_bsum[blockIdx.x] = sm[255];
}

// merged: per-block prefix of block sums (by reduction) + offsets + dinv
__global__ void k_scanC() {
    __shared__ int sm[256];
    int t = threadIdx.x;
    int bid = blockIdx.x;
    int v = 0;
    if (t < bid) v += g_bsum[t];
    if (t + 256 < bid) v += g_bsum[t + 256];
    sm[t] = v;
    __syncthreads();
#pragma unroll
    for (int o = 128; o > 0; o >>= 1) {
        if (t < o) sm[t] += sm[t + o];
        __syncthreads();
    }
    int bbase = sm[0];
    int idx = bid * 256 + t;
    if (idx < NN) {
        int o = g_offtmp[idx] + bbase;
        g_off[idx] = o;
        g_cur[idx] = o;
        g_dinv[idx] = rsqrtf((float)(g_degi[idx] + 1));  // +1 self loop
    }
}

__global__ void k_fill(const int* __restrict__ ei) {
    int e = blockIdx.x * blockDim.x + threadIdx.x;
    if (e < EE) {
        int d = __ldg(&ei[EE + e]);
        int pos = atomicAdd(&g_cur[d], 1);
        g_csr[pos] = make_int2(__ldg(&ei[e]), e);
    }
}

// float4 smem copy helper (stride = block threads)
__device__ __forceinline__ void cp4(float* dst, const float* src, int nfl,
                                    int tid, int nt) {
    const float4* s = (const float4*)src;
    float4* d = (float4*)dst;
    for (int i = tid; i < nfl / 4; i += nt) d[i] = s[i];
}

// ================== node GEMM kernels: 128 threads, 32 nodes/block ===========

// ---------------- K1: h0 = relu(x@We+be); g1' = (h0@Wc1)*dinv ----------------
__global__ __launch_bounds__(128) void k_embed(const float* __restrict__ x,
                                               const float* __restrict__ We,
                                               const float* __restrict__ be,
                                               const float* __restrict__ Wc1) {
    const int tid = threadIdx.x;
    const int j0 = (tid & 15) * 4;
    const int n0 = (tid >> 4) * 4;
    const int base = blockIdx.x * NPB;

    __shared__ float sWe[FN * HH];
    __shared__ float sWc[HH * HH];
    __shared__ float xs[NPB * FN];
    __shared__ float hs[NPB * HH];

    cp4(sWe, We, FN * HH, tid, 128);
    cp4(sWc, Wc1, HH * HH, tid, 128);
    cp4(xs, x + (long)base * FN, NPB * FN, tid, 128);
    __syncthreads();

    float a[4][4] = {};
#pragma unroll
    for (int mg = 0; mg < FN / 4; mg++) {
        float4 v[4];
#pragma unroll
        for (int r = 0; r < 4; r++) v[r] = *(const float4*)&xs[(n0 + r) * FN + mg * 4];
#pragma unroll
        for (int mm = 0; mm < 4; mm++) {
            float4 w = *(const float4*)&sWe[(mg * 4 + mm) * HH + j0];
#pragma unroll
            for (int r = 0; r < 4; r++) {
                float xv = ((const float*)&v[r])[mm];
                a[r][0] = fmaf(xv, w.x, a[r][0]);
                a[r][1] = fmaf(xv, w.y, a[r][1]);
                a[r][2] = fmaf(xv, w.z, a[r][2]);
                a[r][3] = fmaf(xv, w.w, a[r][3]);
            }
        }
    }
    {
        float4 bb = *(const float4*)&be[j0];
#pragma unroll
        for (int r = 0; r < 4; r++) {
            float4 h;
            h.x = fmaxf(a[r][0] + bb.x, 0.f);
            h.y = fmaxf(a[r][1] + bb.y, 0.f);
            h.z = fmaxf(a[r][2] + bb.z, 0.f);
            h.w = fmaxf(a[r][3] + bb.w, 0.f);
            *(float4*)&hs[(n0 + r) * HH + j0] = h;
        }
    }
    __syncthreads();

    float g[4][4] = {};
#pragma unroll
    for (int mg = 0; mg < HH / 4; mg++) {
        float4 v[4];
#pragma unroll
        for (int r = 0; r < 4; r++) v[r] = *(const float4*)&hs[(n0 + r) * HH + mg * 4];
#pragma unroll
        for (int mm = 0; mm < 4; mm++) {
            float4 w = *(const float4*)&sWc[(mg * 4 + mm) * HH + j0];
#pragma unroll
            for (int r = 0; r < 4; r++) {
                float xv = ((const float*)&v[r])[mm];
                g[r][0] = fmaf(xv, w.x, g[r][0]);
                g[r][1] = fmaf(xv, w.y, g[r][1]);
                g[r][2] = fmaf(xv, w.z, g[r][2]);
                g[r][3] = fmaf(xv, w.w, g[r][3]);
            }
        }
    }
#pragma unroll
    for (int r = 0; r < 4; r++) {
        float di = g_dinv[base + n0 + r];
        *(float4*)&g_g[(long)(base + n0 + r) * HH + j0] =
            make_float4(g[r][0] * di, g[r][1] * di, g[r][2] * di, g[r][3] * di);
    }
}

// ---------------- gather-aggregate: acc[n] = g'[n] + sum_{s->n} g'[s] --------
__global__ __launch_bounds__(256) void k_gather() {
    const int tid = threadIdx.x;
    const int p = tid & 15;
    const int grp = tid >> 4;
    const int n = blockIdx.x * 16 + grp;
    const unsigned hm = 0xFFFFu << (tid & 16);

    float4 acc = *(const float4*)&g_g[(long)n * HH + p * 4];  // self loop
    const int beg = g_off[n];
    const int end = beg + g_degi[n];

    for (int b = beg; b < end; b += 16) {
        int rem = end - b;
        int cnt = rem < 16 ? rem : 16;
        int myi = (p < cnt) ? __ldg(&g_csr[b + p]).x : 0;
        for (int k = 0; k < cnt; k++) {
            int s = __shfl_sync(hm, myi, k, 16);
            float4 v = __ldg(reinterpret_cast<const float4*>(&g_g[(long)s * HH]) + p);
            acc.x += v.x; acc.y += v.y; acc.z += v.z; acc.w += v.w;
        }
    }
    *(float4*)&g_acc[(long)n * HH + p * 4] = acc;
}

// ---------------- K3: h1 = relu(acc*dinv + bc1); g2' = (h1@Wc2)*dinv ---------
__global__ __launch_bounds__(128) void k_mid(const float* __restrict__ bc,
                                             const float* __restrict__ Wc) {
    const int tid = threadIdx.x;
    const int j0 = (tid & 15) * 4;
    const int n0 = (tid >> 4) * 4;
    const int base = blockIdx.x * NPB;

    __shared__ float sWc[HH * HH];
    __shared__ float hs[NPB * HH];

    cp4(sWc, Wc, HH * HH, tid, 128);
    {
        const float4* acc4 = (const float4*)&g_acc[(long)base * HH];
        const float4* bc4 = (const float4*)bc;
        float4* hs4 = (float4*)hs;
        for (int i = tid; i < NPB * HH / 4; i += 128) {
            int row = i >> 4;
            float di = g_dinv[base + row];
            float4 v = acc4[i];
            float4 b = bc4[i & 15];
            v.x = fmaxf(fmaf(v.x, di, b.x), 0.f);
            v.y = fmaxf(fmaf(v.y, di, b.y), 0.f);
            v.z = fmaxf(fmaf(v.z, di, b.z), 0.f);
            v.w = fmaxf(fmaf(v.w, di, b.w), 0.f);
            hs4[i] = v;
        }
    }
    __syncthreads();

    float g[4][4] = {};
#pragma unroll
    for (int mg = 0; mg < HH / 4; mg++) {
        float4 v[4];
#pragma unroll
        for (int r = 0; r < 4; r++) v[r] = *(const float4*)&hs[(n0 + r) * HH + mg * 4];
#pragma unroll
        for (int mm = 0; mm < 4; mm++) {
            float4 w = *(const float4*)&sWc[(mg * 4 + mm) * HH + j0];
#pragma unroll
            for (int r = 0; r < 4; r++) {
                float xv = ((const float*)&v[r])[mm];
                g[r][0] = fmaf(xv, w.x, g[r][0]);
                g[r][1] = fmaf(xv, w.y, g[r][1]);
                g[r][2] = fmaf(xv, w.z, g[r][2]);
                g[r][3] = fmaf(xv, w.w, g[r][3]);
            }
        }
    }
#pragma unroll
    for (int r = 0; r < 4; r++) {
        float di = g_dinv[base + n0 + r];
        *(float4*)&g_g[(long)(base + n0 + r) * HH + j0] =
            make_float4(g[r][0] * di, g[r][1] * di, g[r][2] * di, g[r][3] * di);
    }
}

// ---------------- K5: h2 = relu(acc*dinv + bc2); a,b = h2 @ Wp1[0:128] -------
__global__ __launch_bounds__(128) void k_node_final(const float* __restrict__ bc2,
                                                    const float* __restrict__ Wp1) {
    const int tid = threadIdx.x;
    const int j0 = (tid & 15) * 4;
    const int n0 = (tid >> 4) * 4;
    const int base = blockIdx.x * NPB;

    __shared__ float sWa[HH * HH];
    __shared__ float sWb[HH * HH];
    __shared__ float hs[NPB * HH];

    cp4(sWa, Wp1, HH * HH, tid, 128);
    cp4(sWb, Wp1 + HH * HH, HH * HH, tid, 128);
    {
        const float4* acc4 = (const float4*)&g_acc[(long)base * HH];
        const float4* bc4 = (const float4*)bc2;
        float4* hs4 = (float4*)hs;
        for (int i = tid; i < NPB * HH / 4; i += 128) {
            int row = i >> 4;
            float di = g_dinv[base + row];
            float4 v = acc4[i];
            float4 b = bc4[i & 15];
            v.x = fmaxf(fmaf(v.x, di, b.x), 0.f);
            v.y = fmaxf(fmaf(v.y, di, b.y), 0.f);
            v.z = fmaxf(fmaf(v.z, di, b.z), 0.f);
            v.w = fmaxf(fmaf(v.w, di, b.w), 0.f);
            hs4[i] = v;
        }
    }
    __syncthreads();

    float A[4][4] = {};
    float B[4][4] = {};
#pragma unroll
    for (int mg = 0; mg < HH / 4; mg++) {
        float4 v[4];
#pragma unroll
        for (int r = 0; r < 4; r++) v[r] = *(const float4*)&hs[(n0 + r) * HH + mg * 4];
#pragma unroll
        for (int mm = 0; mm < 4; mm++) {
            int m = mg * 4 + mm;
            float4 wa = *(const float4*)&sWa[m * HH + j0];
            float4 wb = *(const float4*)&sWb[m * HH + j0];
#pragma unroll
            for (int r = 0; r < 4; r++) {
                float xv = ((const float*)&v[r])[mm];
                A[r][0] = fmaf(xv, wa.x, A[r][0]);
                A[r][1] = fmaf(xv, wa.y, A[r][1]);
                A[r][2] = fmaf(xv, wa.z, A[r][2]);
                A[r][3] = fmaf(xv, wa.w, A[r][3]);
                B[r][0] = fmaf(xv, wb.x, B[r][0]);
                B[r][1] = fmaf(xv, wb.y, B[r][1]);
                B[r][2] = fmaf(xv, wb.z, B[r][2]);
                B[r][3] = fmaf(xv, wb.w, B[r][3]);
            }
        }
    }
#pragma unroll
    for (int r = 0; r < 4; r++) {
        long rr = (long)(base + n0 + r) * HH + j0;
        *(float4*)&g_a[rr] = make_float4(A[r][0], A[r][1], A[r][2], A[r][3]);
        *(float4*)&g_b[rr] = make_float4(B[r][0], B[r][1], B[r][2], B[r][3]);
    }
}

// ---------------- K6: CSR-ordered edge output ---------------------------------
// 16 threads per dst node: b[dst] row loaded once, in-edges iterated.
__global__ __launch_bounds__(256) void k_edge_out(const float* __restrict__ eattr,
                           const float* __restrict__ Wp1,
                           const float* __restrict__ bp1,
                           const float* __restrict__ wp2,
                           const float* __restrict__ bp2,
                           float* __restrict__ out) {
    const int tid = threadIdx.x;
    const int p = tid & 15;
    const int grp = tid >> 4;
    const int n = blockIdx.x * 16 + grp;   // NN % 16 == 0
    const int j0 = p * 4;
    const unsigned hm = 0xFFFFu << (tid & 16);

    float4 wt[FE];
#pragma unroll
    for (int k = 0; k < FE; k++)
        wt[k] = __ldg(reinterpret_cast<const float4*>(&Wp1[(2 * HH + k) * HH + j0]));
    float4 w2 = __ldg(reinterpret_cast<const float4*>(wp2) + p);
    float bias2 = __ldg(bp2);

    // per-node constant part: b[dst] + bp1
    float4 nb;
    {
        float4 bv = *(const float4*)&g_b[(long)n * HH + j0];
        float4 c0 = __ldg(reinterpret_cast<const float4*>(bp1) + p);
        nb = make_float4(bv.x + c0.x, bv.y + c0.y, bv.z + c0.z, bv.w + c0.w);
    }

    const int beg = g_off[n];
    const int end = beg + g_degi[n];

    for (int b0 = beg; b0 < end; b0 += 16) {
        int rem = end - b0;
        int cnt = rem < 16 ? rem : 16;
        int2 se = (p < cnt) ? __ldg(&g_csr[b0 + p]) : make_int2(0, 0);
        for (int k = 0; k < cnt; k++) {
            int s = __shfl_sync(hm, se.x, k, 16);
            int e = __shfl_sync(hm, se.y, k, 16);

            float eav = (p < FE) ? __ldg(&eattr[(long)e * FE + p]) : 0.0f;
            float4 av = __ldg(reinterpret_cast<const float4*>(&g_a[(long)s * HH]) + p);

            float4 c = nb;
#pragma unroll
            for (int q = 0; q < FE; q++) {
                float eq = __shfl_sync(hm, eav, q, 16);
                c.x = fmaf(eq, wt[q].x, c.x);
                c.y = fmaf(eq, wt[q].y, c.y);
                c.z = fmaf(eq, wt[q].z, c.z);
                c.w = fmaf(eq, wt[q].w, c.w);
            }

            float4 z;
            z.x = fmaxf(av.x + c.x, 0.0f);
            z.y = fmaxf(av.y + c.y, 0.0f);
            z.z = fmaxf(av.z + c.z, 0.0f);
            z.w = fmaxf(av.w + c.w, 0.0f);

            float part = z.x * w2.x + z.y * w2.y + z.z * w2.z + z.w * w2.w;
#pragma unroll
            for (int off = 8; off >= 1; off >>= 1)
                part += __shfl_down_sync(hm, part, off, 16);

            if (p == 0) out[e] = part + bias2;
        }
    }
}

// ---------------- host launcher ----------------------------------------------
extern "C" void kernel_launch(void* const* d_in, const int* in_sizes, int n_in,
                              void* d_out, int out_size) {
    const float* x     = (const float*)d_in[0];
    const float* eattr = (const float*)d_in[1];
    const float* We    = (const float*)d_in[2];
    const float* be    = (const float*)d_in[3];
    const float* Wc1   = (const float*)d_in[4];
    const float* bc1   = (const float*)d_in[5];
    const float* Wc2   = (const float*)d_in[6];
    const float* bc2   = (const float*)d_in[7];
    const float* Wp1   = (const float*)d_in[8];
    const float* bp1   = (const float*)d_in[9];
    const float* wp2   = (const float*)d_in[10];
    const float* bp2   = (const float*)d_in[11];
    const int*   ei    = (const int*)d_in[12];
    float* out = (float*)d_out;

    // CSR build prologue (serial part: degrees -> offsets -> dinv)
    k_zero<<<(NN + 255) / 256, 256>>>();
    k_deg<<<(EE + 255) / 256, 256>>>(ei);
    k_scanA<<<NB_SCAN, 256>>>();
    k_scanC<<<NB_SCAN, 256>>>();

    int ngrid = NN / NPB;          // 3125
    int ggrid = NN / 16;           // 6250

    // fork: k_fill (CSR population) runs concurrently with k_embed
    cudaStream_t s2;
    cudaStreamCreate(&s2);
    cudaEvent_t evFork, evJoin;
    cudaEventCreateWithFlags(&evFork, cudaEventDisableTiming);
    cudaEventCreateWithFlags(&evJoin, cudaEventDisableTiming);

    cudaEventRecord(evFork, 0);
    cudaStreamWaitEvent(s2, evFork, 0);
    k_fill<<<(EE + 255) / 256, 256, 0, s2>>>(ei);
    cudaEventRecord(evJoin, s2);

    k_embed<<<ngrid, 128>>>(x, We, be, Wc1);

    cudaStreamWaitEvent(0, evJoin, 0);

    k_gather<<<ggrid, 256>>>();
    k_mid<<<ngrid, 128>>>(bc1, Wc2);
    k_gather<<<ggrid, 256>>>();
    k_node_final<<<ngrid, 128>>>(bc2, Wp1);

    k_edge_out<<<ggrid, 256>>>(eattr, Wp1, bp1, wp2, bp2, out);

    cudaEventDestroy(evFork);
    cudaEventDestroy(evJoin);
    cudaStreamDestroy(s2);
}

// round 9
// speedup vs baseline: 1.3551x; 1.3551x over previous
#include <cuda_runtime.h>
#include <cuda_bf16.h>
#include <stdint.h>

#define NN 100000
#define EE 1600000
#define FN 32
#define FE 8
#define HH 64
#define NPB 32
#define NB_SCAN 391   // ceil(NN/256)

// ---------------- scratch (device globals) ------------------------------------
__device__ float g_g[NN * HH];    // g' = (h@W) * dinv[src-side]
__device__ float g_acc[NN * HH];  // aggregated (self + in-edges)
__device__ float g_a[NN * HH];
__device__ float g_b[NN * HH];
__device__ float g_dinv[NN];
__device__ int   g_degi[NN];
__device__ int   g_off[NN];
__device__ int   g_offtmp[NN];
__device__ int   g_cur[NN];
__device__ int   g_bsum[512];
__device__ int   g_csr[EE];       // src node of each in-edge, grouped by dst

// ---------------- degree / norm / CSR build -----------------------------------
__global__ void k_zero() {
    int n = blockIdx.x * blockDim.x + threadIdx.x;
    if (n < NN) g_degi[n] = 0;
}

__global__ void k_deg(const int* __restrict__ ei) {
    int e = blockIdx.x * blockDim.x + threadIdx.x;
    if (e < EE) atomicAdd(&g_degi[__ldg(&ei[EE + e])], 1);
}

// block-level inclusive scan (Hillis-Steele), emit exclusive + block sums
__global__ void k_scanA() {
    __shared__ int sm[256];
    int t = threadIdx.x;
    int idx = blockIdx.x * 256 + t;
    int v = (idx < NN) ? g_degi[idx] : 0;
    sm[t] = v;
    __syncthreads();
#pragma unroll
    for (int o = 1; o < 256; o <<= 1) {
        int x = (t >= o) ? sm[t - o] : 0;
        __syncthreads();
        sm[t] += x;
        __syncthreads();
    }
    if (idx < NN) g_offtmp[idx] = sm[t] - v;
    if (t == 255) g_bsum[blockIdx.x] = sm[255];
}

// merged: per-block prefix of block sums (by reduction) + offsets + dinv
__global__ void k_scanC() {
    __shared__ int sm[256];
    int t = threadIdx.x;
    int bid = blockIdx.x;
    int v = 0;
    if (t < bid) v += g_bsum[t];
    if (t + 256 < bid) v += g_bsum[t + 256];
    sm[t] = v;
    __syncthreads();
#pragma unroll
    for (int o = 128; o > 0; o >>= 1) {
        if (t < o) sm[t] += sm[t + o];
        __syncthreads();
    }
    int bbase = sm[0];
    int idx = bid * 256 + t;
    if (idx < NN) {
        int o = g_offtmp[idx] + bbase;
        g_off[idx] = o;
        g_cur[idx] = o;
        g_dinv[idx] = rsqrtf((float)(g_degi[idx] + 1));  // +1 self loop
    }
}

__global__ void k_fill(const int* __restrict__ ei) {
    int e = blockIdx.x * blockDim.x + threadIdx.x;
    if (e < EE) {
        int d = __ldg(&ei[EE + e]);
        int pos = atomicAdd(&g_cur[d], 1);
        g_csr[pos] = __ldg(&ei[e]);
    }
}

// float4 smem copy helper (stride = block threads)
__device__ __forceinline__ void cp4(float* dst, const float* src, int nfl,
                                    int tid, int nt) {
    const float4* s = (const float4*)src;
    float4* d = (float4*)dst;
    for (int i = tid; i < nfl / 4; i += nt) d[i] = s[i];
}

// ================== node GEMM kernels: 128 threads, 32 nodes/block ===========

// ---------------- K1: h0 = relu(x@We+be); g1' = (h0@Wc1)*dinv ----------------
__global__ __launch_bounds__(128) void k_embed(const float* __restrict__ x,
                                               const float* __restrict__ We,
                                               const float* __restrict__ be,
                                               const float* __restrict__ Wc1) {
    const int tid = threadIdx.x;
    const int j0 = (tid & 15) * 4;
    const int n0 = (tid >> 4) * 4;
    const int base = blockIdx.x * NPB;

    __shared__ float sWe[FN * HH];
    __shared__ float sWc[HH * HH];
    __shared__ float xs[NPB * FN];
    __shared__ float hs[NPB * HH];

    cp4(sWe, We, FN * HH, tid, 128);
    cp4(sWc, Wc1, HH * HH, tid, 128);
    cp4(xs, x + (long)base * FN, NPB * FN, tid, 128);
    __syncthreads();

    float a[4][4] = {};
#pragma unroll
    for (int mg = 0; mg < FN / 4; mg++) {
        float4 v[4];
#pragma unroll
        for (int r = 0; r < 4; r++) v[r] = *(const float4*)&xs[(n0 + r) * FN + mg * 4];
#pragma unroll
        for (int mm = 0; mm < 4; mm++) {
            float4 w = *(const float4*)&sWe[(mg * 4 + mm) * HH + j0];
#pragma unroll
            for (int r = 0; r < 4; r++) {
                float xv = ((const float*)&v[r])[mm];
                a[r][0] = fmaf(xv, w.x, a[r][0]);
                a[r][1] = fmaf(xv, w.y, a[r][1]);
                a[r][2] = fmaf(xv, w.z, a[r][2]);
                a[r][3] = fmaf(xv, w.w, a[r][3]);
            }
        }
    }
    {
        float4 bb = *(const float4*)&be[j0];
#pragma unroll
        for (int r = 0; r < 4; r++) {
            float4 h;
            h.x = fmaxf(a[r][0] + bb.x, 0.f);
            h.y = fmaxf(a[r][1] + bb.y, 0.f);
            h.z = fmaxf(a[r][2] + bb.z, 0.f);
            h.w = fmaxf(a[r][3] + bb.w, 0.f);
            *(float4*)&hs[(n0 + r) * HH + j0] = h;
        }
    }
    __syncthreads();

    float g[4][4] = {};
#pragma unroll
    for (int mg = 0; mg < HH / 4; mg++) {
        float4 v[4];
#pragma unroll
        for (int r = 0; r < 4; r++) v[r] = *(const float4*)&hs[(n0 + r) * HH + mg * 4];
#pragma unroll
        for (int mm = 0; mm < 4; mm++) {
            float4 w = *(const float4*)&sWc[(mg * 4 + mm) * HH + j0];
#pragma unroll
            for (int r = 0; r < 4; r++) {
                float xv = ((const float*)&v[r])[mm];
                g[r][0] = fmaf(xv, w.x, g[r][0]);
                g[r][1] = fmaf(xv, w.y, g[r][1]);
                g[r][2] = fmaf(xv, w.z, g[r][2]);
                g[r][3] = fmaf(xv, w.w, g[r][3]);
            }
        }
    }
#pragma unroll
    for (int r = 0; r < 4; r++) {
        float di = g_dinv[base + n0 + r];
        *(float4*)&g_g[(long)(base + n0 + r) * HH + j0] =
            make_float4(g[r][0] * di, g[r][1] * di, g[r][2] * di, g[r][3] * di);
    }
}

// ---------------- gather-aggregate: acc[n] = g'[n] + sum_{s->n} g'[s] --------
__global__ __launch_bounds__(256) void k_gather() {
    const int tid = threadIdx.x;
    const int p = tid & 15;
    const int grp = tid >> 4;
    const int n = blockIdx.x * 16 + grp;
    const unsigned hm = 0xFFFFu << (tid & 16);

    float4 acc = *(const float4*)&g_g[(long)n * HH + p * 4];  // self loop
    const int beg = g_off[n];
    const int end = beg + g_degi[n];

    for (int b = beg; b < end; b += 16) {
        int rem = end - b;
        int cnt = rem < 16 ? rem : 16;
        int myi = (p < cnt) ? __ldg(&g_csr[b + p]) : 0;
#pragma unroll 4
        for (int k = 0; k < cnt; k++) {
            int s = __shfl_sync(hm, myi, k, 16);
            float4 v = __ldg(reinterpret_cast<const float4*>(&g_g[(long)s * HH]) + p);
            acc.x += v.x; acc.y += v.y; acc.z += v.z; acc.w += v.w;
        }
    }
    *(float4*)&g_acc[(long)n * HH + p * 4] = acc;
}

// ---------------- K3: h1 = relu(acc*dinv + bc1); g2' = (h1@Wc2)*dinv ---------
__global__ __launch_bounds__(128) void k_mid(const float* __restrict__ bc,
                                             const float* __restrict__ Wc) {
    const int tid = threadIdx.x;
    const int j0 = (tid & 15) * 4;
    const int n0 = (tid >> 4) * 4;
    const int base = blockIdx.x * NPB;

    __shared__ float sWc[HH * HH];
    __shared__ float hs[NPB * HH];

    cp4(sWc, Wc, HH * HH, tid, 128);
    {
        const float4* acc4 = (const float4*)&g_acc[(long)base * HH];
        const float4* bc4 = (const float4*)bc;
        float4* hs4 = (float4*)hs;
        for (int i = tid; i < NPB * HH / 4; i += 128) {
            int row = i >> 4;
            float di = g_dinv[base + row];
            float4 v = acc4[i];
            float4 b = bc4[i & 15];
            v.x = fmaxf(fmaf(v.x, di, b.x), 0.f);
            v.y = fmaxf(fmaf(v.y, di, b.y), 0.f);
            v.z = fmaxf(fmaf(v.z, di, b.z), 0.f);
            v.w = fmaxf(fmaf(v.w, di, b.w), 0.f);
            hs4[i] = v;
        }
    }
    __syncthreads();

    float g[4][4] = {};
#pragma unroll
    for (int mg = 0; mg < HH / 4; mg++) {
        float4 v[4];
#pragma unroll
        for (int r = 0; r < 4; r++) v[r] = *(const float4*)&hs[(n0 + r) * HH + mg * 4];
#pragma unroll
        for (int mm = 0; mm < 4; mm++) {
            float4 w = *(const float4*)&sWc[(mg * 4 + mm) * HH + j0];
#pragma unroll
            for (int r = 0; r < 4; r++) {
                float xv = ((const float*)&v[r])[mm];
                g[r][0] = fmaf(xv, w.x, g[r][0]);
                g[r][1] = fmaf(xv, w.y, g[r][1]);
                g[r][2] = fmaf(xv, w.z, g[r][2]);
                g[r][3] = fmaf(xv, w.w, g[r][3]);
            }
        }
    }
#pragma unroll
    for (int r = 0; r < 4; r++) {
        float di = g_dinv[base + n0 + r];
        *(float4*)&g_g[(long)(base + n0 + r) * HH + j0] =
            make_float4(g[r][0] * di, g[r][1] * di, g[r][2] * di, g[r][3] * di);
    }
}

// ---------------- K5: h2 = relu(acc*dinv + bc2); a,b = h2 @ Wp1[0:128] -------
__global__ __launch_bounds__(128) void k_node_final(const float* __restrict__ bc2,
                                                    const float* __restrict__ Wp1) {
    const int tid = threadIdx.x;
    const int j0 = (tid & 15) * 4;
    const int n0 = (tid >> 4) * 4;
    const int base = blockIdx.x * NPB;

    __shared__ float sWa[HH * HH];
    __shared__ float sWb[HH * HH];
    __shared__ float hs[NPB * HH];

    cp4(sWa, Wp1, HH * HH, tid, 128);
    cp4(sWb, Wp1 + HH * HH, HH * HH, tid, 128);
    {
        const float4* acc4 = (const float4*)&g_acc[(long)base * HH];
        const float4* bc4 = (const float4*)bc2;
        float4* hs4 = (float4*)hs;
        for (int i = tid; i < NPB * HH / 4; i += 128) {
            int row = i >> 4;
            float di = g_dinv[base + row];
            float4 v = acc4[i];
            float4 b = bc4[i & 15];
            v.x = fmaxf(fmaf(v.x, di, b.x), 0.f);
            v.y = fmaxf(fmaf(v.y, di, b.y), 0.f);
            v.z = fmaxf(fmaf(v.z, di, b.z), 0.f);
            v.w = fmaxf(fmaf(v.w, di, b.w), 0.f);
            hs4[i] = v;
        }
    }
    __syncthreads();

    float A[4][4] = {};
    float B[4][4] = {};
#pragma unroll
    for (int mg = 0; mg < HH / 4; mg++) {
        float4 v[4];
#pragma unroll
        for (int r = 0; r < 4; r++) v[r] = *(const float4*)&hs[(n0 + r) * HH + mg * 4];
#pragma unroll
        for (int mm = 0; mm < 4; mm++) {
            int m = mg * 4 + mm;
            float4 wa = *(const float4*)&sWa[m * HH + j0];
            float4 wb = *(const float4*)&sWb[m * HH + j0];
#pragma unroll
            for (int r = 0; r < 4; r++) {
                float xv = ((const float*)&v[r])[mm];
                A[r][0] = fmaf(xv, wa.x, A[r][0]);
                A[r][1] = fmaf(xv, wa.y, A[r][1]);
                A[r][2] = fmaf(xv, wa.z, A[r][2]);
                A[r][3] = fmaf(xv, wa.w, A[r][3]);
                B[r][0] = fmaf(xv, wb.x, B[r][0]);
                B[r][1] = fmaf(xv, wb.y, B[r][1]);
                B[r][2] = fmaf(xv, wb.z, B[r][2]);
                B[r][3] = fmaf(xv, wb.w, B[r][3]);
            }
        }
    }
#pragma unroll
    for (int r = 0; r < 4; r++) {
        long rr = (long)(base + n0 + r) * HH + j0;
        *(float4*)&g_a[rr] = make_float4(A[r][0], A[r][1], A[r][2], A[r][3]);
        *(float4*)&g_b[rr] = make_float4(B[r][0], B[r][1], B[r][2], B[r][3]);
    }
}

// ---------------- K6: per-edge output, 4 edges per 16-thread group -----------
#define EPT 4
__global__ __launch_bounds__(256) void k_edge_out(const int* __restrict__ ei,
                           const float* __restrict__ eattr,
                           const float* __restrict__ Wp1,
                           const float* __restrict__ bp1,
                           const float* __restrict__ wp2,
                           const float* __restrict__ bp2,
                           float* __restrict__ out) {
    const int tid = threadIdx.x;
    const int p = tid & 15;
    const int grp = tid >> 4;
    const int j0 = p * 4;
    long e0 = ((long)blockIdx.x * 16 + grp) * EPT;

    float4 wt[FE];
#pragma unroll
    for (int k = 0; k < FE; k++)
        wt[k] = __ldg(reinterpret_cast<const float4*>(&Wp1[(2 * HH + k) * HH + j0]));
    float4 c0 = __ldg(reinterpret_cast<const float4*>(bp1) + p);
    float4 w2 = __ldg(reinterpret_cast<const float4*>(wp2) + p);
    float bias2 = __ldg(bp2);

    float res[EPT];
#pragma unroll
    for (int t = 0; t < EPT; t++) {
        long e = e0 + t;
        int s = __ldg(&ei[e]);
        int d = __ldg(&ei[EE + e]);
        float eav = (p < FE) ? __ldg(&eattr[e * FE + p]) : 0.0f;

        float4 av = __ldg(reinterpret_cast<const float4*>(&g_a[(long)s * HH]) + p);
        float4 bv = __ldg(reinterpret_cast<const float4*>(&g_b[(long)d * HH]) + p);

        float4 c = c0;
#pragma unroll
        for (int k = 0; k < FE; k++) {
            float ek = __shfl_sync(0xffffffffu, eav, k, 16);
            c.x = fmaf(ek, wt[k].x, c.x);
            c.y = fmaf(ek, wt[k].y, c.y);
            c.z = fmaf(ek, wt[k].z, c.z);
            c.w = fmaf(ek, wt[k].w, c.w);
        }

        float4 z;
        z.x = fmaxf(av.x + bv.x + c.x, 0.0f);
        z.y = fmaxf(av.y + bv.y + c.y, 0.0f);
        z.z = fmaxf(av.z + bv.z + c.z, 0.0f);
        z.w = fmaxf(av.w + bv.w + c.w, 0.0f);

        float part = z.x * w2.x + z.y * w2.y + z.z * w2.z + z.w * w2.w;
#pragma unroll
        for (int off = 8; off >= 1; off >>= 1)
            part += __shfl_down_sync(0xffffffffu, part, off, 16);

        res[t] = part + bias2;
    }
    if (p == 0)
        *reinterpret_cast<float4*>(&out[e0]) =
            make_float4(res[0], res[1], res[2], res[3]);
}

// ---------------- host launcher ----------------------------------------------
extern "C" void kernel_launch(void* const* d_in, const int* in_sizes, int n_in,
                              void* d_out, int out_size) {
    const float* x     = (const float*)d_in[0];
    const float* eattr = (const float*)d_in[1];
    const float* We    = (const float*)d_in[2];
    const float* be    = (const float*)d_in[3];
    const float* Wc1   = (const float*)d_in[4];
    const float* bc1   = (const float*)d_in[5];
    const float* Wc2   = (const float*)d_in[6];
    const float* bc2   = (const float*)d_in[7];
    const float* Wp1   = (const float*)d_in[8];
    const float* bp1   = (const float*)d_in[9];
    const float* wp2   = (const float*)d_in[10];
    const float* bp2   = (const float*)d_in[11];
    const int*   ei    = (const int*)d_in[12];
    float* out = (float*)d_out;

    // CSR build prologue (serial part: degrees -> offsets -> dinv)
    k_zero<<<(NN + 255) / 256, 256>>>();
    k_deg<<<(EE + 255) / 256, 256>>>(ei);
    k_scanA<<<NB_SCAN, 256>>>();
    k_scanC<<<NB_SCAN, 256>>>();

    int ngrid = NN / NPB;          // 3125
    int ggrid = NN / 16;           // 6250

    // fork: k_fill (CSR population) runs concurrently with k_embed
    cudaStream_t s2;
    cudaStreamCreate(&s2);
    cudaEvent_t evFork, evJoin;
    cudaEventCreateWithFlags(&evFork, cudaEventDisableTiming);
    cudaEventCreateWithFlags(&evJoin, cudaEventDisableTiming);

    cudaEventRecord(evFork, 0);
    cudaStreamWaitEvent(s2, evFork, 0);
    k_fill<<<(EE + 255) / 256, 256, 0, s2>>>(ei);
    cudaEventRecord(evJoin, s2);

    k_embed<<<ngrid, 128>>>(x, We, be, Wc1);

    cudaStreamWaitEvent(0, evJoin, 0);

    k_gather<<<ggrid, 256>>>();
    k_mid<<<ngrid, 128>>>(bc1, Wc2);
    k_gather<<<ggrid, 256>>>();
    k_node_final<<<ngrid, 128>>>(bc2, Wp1);

    k_edge_out<<<EE / (16 * EPT), 256>>>(ei, eattr, Wp1, bp1, wp2, bp2, out);

    cudaEventDestroy(evFork);
    cudaEventDestroy(evJoin);
    cudaStreamDestroy(s2);
}

// round 10
// speedup vs baseline: 1.4632x; 1.0797x over previous
#include <cuda_runtime.h>
#include <cuda_bf16.h>
#include <cuda_fp16.h>
#include <stdint.h>

#define NN 100000
#define EE 1600000
#define FN 32
#define FE 8
#define HH 64
#define NPB 32
#define NB_SCAN 391   // ceil(NN/256)

// ---------------- scratch (device globals) ------------------------------------
__device__ __half g_g[NN * HH];   // fp16: g' = (h@W) * dinv (gathered randomly)
__device__ float  g_acc[NN * HH]; // fp32 aggregation target (linear access)
__device__ __half g_a[NN * HH];   // fp16: h2 @ W_p1[0:64]
__device__ __half g_b[NN * HH];   // fp16: h2 @ W_p1[64:128]
__device__ float  g_dinv[NN];
__device__ int    g_degi[NN];
__device__ int    g_off[NN];
__device__ int    g_offtmp[NN];
__device__ int    g_cur[NN];
__device__ int    g_bsum[512];
__device__ int    g_csr[EE];      // src node of each in-edge, grouped by dst

// ---------------- degree / norm / CSR build -----------------------------------
__global__ void k_zero() {
    int n = blockIdx.x * blockDim.x + threadIdx.x;
    if (n < NN) g_degi[n] = 0;
}

__global__ void k_deg(const int* __restrict__ ei) {
    int e = blockIdx.x * blockDim.x + threadIdx.x;
    if (e < EE) atomicAdd(&g_degi[__ldg(&ei[EE + e])], 1);
}

__global__ void k_scanA() {
    __shared__ int sm[256];
    int t = threadIdx.x;
    int idx = blockIdx.x * 256 + t;
    int v = (idx < NN) ? g_degi[idx] : 0;
    sm[t] = v;
    __syncthreads();
#pragma unroll
    for (int o = 1; o < 256; o <<= 1) {
        int x = (t >= o) ? sm[t - o] : 0;
        __syncthreads();
        sm[t] += x;
        __syncthreads();
    }
    if (idx < NN) g_offtmp[idx] = sm[t] - v;
    if (t == 255) g_bsum[blockIdx.x] = sm[255];
}

__global__ void k_scanC() {
    __shared__ int sm[256];
    int t = threadIdx.x;
    int bid = blockIdx.x;
    int v = 0;
    if (t < bid) v += g_bsum[t];
    if (t + 256 < bid) v += g_bsum[t + 256];
    sm[t] = v;
    __syncthreads();
#pragma unroll
    for (int o = 128; o > 0; o >>= 1) {
        if (t < o) sm[t] += sm[t + o];
        __syncthreads();
    }
    int bbase = sm[0];
    int idx = bid * 256 + t;
    if (idx < NN) {
        int o = g_offtmp[idx] + bbase;
        g_off[idx] = o;
        g_cur[idx] = o;
        g_dinv[idx] = rsqrtf((float)(g_degi[idx] + 1));  // +1 self loop
    }
}

__global__ void k_fill(const int* __restrict__ ei) {
    int e = blockIdx.x * blockDim.x + threadIdx.x;
    if (e < EE) {
        int d = __ldg(&ei[EE + e]);
        int pos = atomicAdd(&g_cur[d], 1);
        g_csr[pos] = __ldg(&ei[e]);
    }
}

// float4 smem copy helper
__device__ __forceinline__ void cp4(float* dst, const float* src, int nfl,
                                    int tid, int nt) {
    const float4* s = (const float4*)src;
    float4* d = (float4*)dst;
    for (int i = tid; i < nfl / 4; i += nt) d[i] = s[i];
}

// pack 4 fp32 -> 4 fp16 (uint2)
__device__ __forceinline__ uint2 pack_h4(float a, float b, float c, float d) {
    __half2 lo = __floats2half2_rn(a, b);
    __half2 hi = __floats2half2_rn(c, d);
    uint2 r;
    r.x = *reinterpret_cast<unsigned*>(&lo);
    r.y = *reinterpret_cast<unsigned*>(&hi);
    return r;
}

// unpack uint2 (4 fp16) -> float4
__device__ __forceinline__ float4 unpack_h4(uint2 r) {
    float2 lo = __half22float2(*reinterpret_cast<__half2*>(&r.x));
    float2 hi = __half22float2(*reinterpret_cast<__half2*>(&r.y));
    return make_float4(lo.x, lo.y, hi.x, hi.y);
}

// ================== node GEMM kernels: 128 threads, 32 nodes/block ===========

// ---------------- K1: h0 = relu(x@We+be); g1' = (h0@Wc1)*dinv (fp16 store) ---
__global__ __launch_bounds__(128) void k_embed(const float* __restrict__ x,
                                               const float* __restrict__ We,
                                               const float* __restrict__ be,
                                               const float* __restrict__ Wc1) {
    const int tid = threadIdx.x;
    const int j0 = (tid & 15) * 4;
    const int n0 = (tid >> 4) * 4;
    const int base = blockIdx.x * NPB;

    __shared__ float sWe[FN * HH];
    __shared__ float sWc[HH * HH];
    __shared__ float xs[NPB * FN];
    __shared__ float hs[NPB * HH];

    cp4(sWe, We, FN * HH, tid, 128);
    cp4(sWc, Wc1, HH * HH, tid, 128);
    cp4(xs, x + (long)base * FN, NPB * FN, tid, 128);
    __syncthreads();

    float a[4][4] = {};
#pragma unroll
    for (int mg = 0; mg < FN / 4; mg++) {
        float4 v[4];
#pragma unroll
        for (int r = 0; r < 4; r++) v[r] = *(const float4*)&xs[(n0 + r) * FN + mg * 4];
#pragma unroll
        for (int mm = 0; mm < 4; mm++) {
            float4 w = *(const float4*)&sWe[(mg * 4 + mm) * HH + j0];
#pragma unroll
            for (int r = 0; r < 4; r++) {
                float xv = ((const float*)&v[r])[mm];
                a[r][0] = fmaf(xv, w.x, a[r][0]);
                a[r][1] = fmaf(xv, w.y, a[r][1]);
                a[r][2] = fmaf(xv, w.z, a[r][2]);
                a[r][3] = fmaf(xv, w.w, a[r][3]);
            }
        }
    }
    {
        float4 bb = *(const float4*)&be[j0];
#pragma unroll
        for (int r = 0; r < 4; r++) {
            float4 h;
            h.x = fmaxf(a[r][0] + bb.x, 0.f);
            h.y = fmaxf(a[r][1] + bb.y, 0.f);
            h.z = fmaxf(a[r][2] + bb.z, 0.f);
            h.w = fmaxf(a[r][3] + bb.w, 0.f);
            *(float4*)&hs[(n0 + r) * HH + j0] = h;
        }
    }
    __syncthreads();

    float g[4][4] = {};
#pragma unroll
    for (int mg = 0; mg < HH / 4; mg++) {
        float4 v[4];
#pragma unroll
        for (int r = 0; r < 4; r++) v[r] = *(const float4*)&hs[(n0 + r) * HH + mg * 4];
#pragma unroll
        for (int mm = 0; mm < 4; mm++) {
            float4 w = *(const float4*)&sWc[(mg * 4 + mm) * HH + j0];
#pragma unroll
            for (int r = 0; r < 4; r++) {
                float xv = ((const float*)&v[r])[mm];
                g[r][0] = fmaf(xv, w.x, g[r][0]);
                g[r][1] = fmaf(xv, w.y, g[r][1]);
                g[r][2] = fmaf(xv, w.z, g[r][2]);
                g[r][3] = fmaf(xv, w.w, g[r][3]);
            }
        }
    }
#pragma unroll
    for (int r = 0; r < 4; r++) {
        float di = g_dinv[base + n0 + r];
        *reinterpret_cast<uint2*>(&g_g[(long)(base + n0 + r) * HH + j0]) =
            pack_h4(g[r][0] * di, g[r][1] * di, g[r][2] * di, g[r][3] * di);
    }
}

// ---------------- gather-aggregate: acc[n] = g'[n] + sum_{s->n} g'[s] --------
__global__ __launch_bounds__(256) void k_gather() {
    const int tid = threadIdx.x;
    const int p = tid & 15;
    const int grp = tid >> 4;
    const int n = blockIdx.x * 16 + grp;
    const unsigned hm = 0xFFFFu << (tid & 16);

    float4 acc = unpack_h4(
        *reinterpret_cast<const uint2*>(&g_g[(long)n * HH + p * 4]));  // self loop
    const int beg = g_off[n];
    const int end = beg + g_degi[n];

    for (int b = beg; b < end; b += 16) {
        int rem = end - b;
        int cnt = rem < 16 ? rem : 16;
        int myi = (p < cnt) ? __ldg(&g_csr[b + p]) : 0;
        for (int k = 0; k < cnt; k++) {
            int s = __shfl_sync(hm, myi, k, 16);
            uint2 raw = __ldg(reinterpret_cast<const uint2*>(&g_g[(long)s * HH]) + p);
            float4 v = unpack_h4(raw);
            acc.x += v.x; acc.y += v.y; acc.z += v.z; acc.w += v.w;
        }
    }
    *(float4*)&g_acc[(long)n * HH + p * 4] = acc;
}

// ---------------- K3: h1 = relu(acc*dinv + bc1); g2' = (h1@Wc2)*dinv ---------
__global__ __launch_bounds__(128) void k_mid(const float* __restrict__ bc,
                                             const float* __restrict__ Wc) {
    const int tid = threadIdx.x;
    const int j0 = (tid & 15) * 4;
    const int n0 = (tid >> 4) * 4;
    const int base = blockIdx.x * NPB;

    __shared__ float sWc[HH * HH];
    __shared__ float hs[NPB * HH];

    cp4(sWc, Wc, HH * HH, tid, 128);
    {
        const float4* acc4 = (const float4*)&g_acc[(long)base * HH];
        const float4* bc4 = (const float4*)bc;
        float4* hs4 = (float4*)hs;
        for (int i = tid; i < NPB * HH / 4; i += 128) {
            int row = i >> 4;
            float di = g_dinv[base + row];
            float4 v = acc4[i];
            float4 b = bc4[i & 15];
            v.x = fmaxf(fmaf(v.x, di, b.x), 0.f);
            v.y = fmaxf(fmaf(v.y, di, b.y), 0.f);
            v.z = fmaxf(fmaf(v.z, di, b.z), 0.f);
            v.w = fmaxf(fmaf(v.w, di, b.w), 0.f);
            hs4[i] = v;
        }
    }
    __syncthreads();

    float g[4][4] = {};
#pragma unroll
    for (int mg = 0; mg < HH / 4; mg++) {
        float4 v[4];
#pragma unroll
        for (int r = 0; r < 4; r++) v[r] = *(const float4*)&hs[(n0 + r) * HH + mg * 4];
#pragma unroll
        for (int mm = 0; mm < 4; mm++) {
            float4 w = *(const float4*)&sWc[(mg * 4 + mm) * HH + j0];
#pragma unroll
            for (int r = 0; r < 4; r++) {
                float xv = ((const float*)&v[r])[mm];
                g[r][0] = fmaf(xv, w.x, g[r][0]);
                g[r][1] = fmaf(xv, w.y, g[r][1]);
                g[r][2] = fmaf(xv, w.z, g[r][2]);
                g[r][3] = fmaf(xv, w.w, g[r][3]);
            }
        }
    }
#pragma unroll
    for (int r = 0; r < 4; r++) {
        float di = g_dinv[base + n0 + r];
        *reinterpret_cast<uint2*>(&g_g[(long)(base + n0 + r) * HH + j0]) =
            pack_h4(g[r][0] * di, g[r][1] * di, g[r][2] * di, g[r][3] * di);
    }
}

// ---------------- K5: h2 = relu(acc*dinv + bc2); a,b = h2 @ Wp1[0:128] -------
__global__ __launch_bounds__(128) void k_node_final(const float* __restrict__ bc2,
                                                    const float* __restrict__ Wp1) {
    const int tid = threadIdx.x;
    const int j0 = (tid & 15) * 4;
    const int n0 = (tid >> 4) * 4;
    const int base = blockIdx.x * NPB;

    __shared__ float sWa[HH * HH];
    __shared__ float sWb[HH * HH];
    __shared__ float hs[NPB * HH];

    cp4(sWa, Wp1, HH * HH, tid, 128);
    cp4(sWb, Wp1 + HH * HH, HH * HH, tid, 128);
    {
        const float4* acc4 = (const float4*)&g_acc[(long)base * HH];
        const float4* bc4 = (const float4*)bc2;
        float4* hs4 = (float4*)hs;
        for (int i = tid; i < NPB * HH / 4; i += 128) {
            int row = i >> 4;
            float di = g_dinv[base + row];
            float4 v = acc4[i];
            float4 b = bc4[i & 15];
            v.x = fmaxf(fmaf(v.x, di, b.x), 0.f);
            v.y = fmaxf(fmaf(v.y, di, b.y), 0.f);
            v.z = fmaxf(fmaf(v.z, di, b.z), 0.f);
            v.w = fmaxf(fmaf(v.w, di, b.w), 0.f);
            hs4[i] = v;
        }
    }
    __syncthreads();

    float A[4][4] = {};
    float B[4][4] = {};
#pragma unroll
    for (int mg = 0; mg < HH / 4; mg++) {
        float4 v[4];
#pragma unroll
        for (int r = 0; r < 4; r++) v[r] = *(const float4*)&hs[(n0 + r) * HH + mg * 4];
#pragma unroll
        for (int mm = 0; mm < 4; mm++) {
            int m = mg * 4 + mm;
            float4 wa = *(const float4*)&sWa[m * HH + j0];
            float4 wb = *(const float4*)&sWb[m * HH + j0];
#pragma unroll
            for (int r = 0; r < 4; r++) {
                float xv = ((const float*)&v[r])[mm];
                A[r][0] = fmaf(xv, wa.x, A[r][0]);
                A[r][1] = fmaf(xv, wa.y, A[r][1]);
                A[r][2] = fmaf(xv, wa.z, A[r][2]);
                A[r][3] = fmaf(xv, wa.w, A[r][3]);
                B[r][0] = fmaf(xv, wb.x, B[r][0]);
                B[r][1] = fmaf(xv, wb.y, B[r][1]);
                B[r][2] = fmaf(xv, wb.z, B[r][2]);
                B[r][3] = fmaf(xv, wb.w, B[r][3]);
            }
        }
    }
#pragma unroll
    for (int r = 0; r < 4; r++) {
        long rr = (long)(base + n0 + r) * HH + j0;
        *reinterpret_cast<uint2*>(&g_a[rr]) = pack_h4(A[r][0], A[r][1], A[r][2], A[r][3]);
        *reinterpret_cast<uint2*>(&g_b[rr]) = pack_h4(B[r][0], B[r][1], B[r][2], B[r][3]);
    }
}

// ---------------- K6: per-edge output, 4 edges per 16-thread group -----------
#define EPT 4
__global__ __launch_bounds__(256) void k_edge_out(const int* __restrict__ ei,
                           const float* __restrict__ eattr,
                           const float* __restrict__ Wp1,
                           const float* __restrict__ bp1,
                           const float* __restrict__ wp2,
                           const float* __restrict__ bp2,
                           float* __restrict__ out) {
    const int tid = threadIdx.x;
    const int p = tid & 15;
    const int grp = tid >> 4;
    const int j0 = p * 4;
    long e0 = ((long)blockIdx.x * 16 + grp) * EPT;

    float4 wt[FE];
#pragma unroll
    for (int k = 0; k < FE; k++)
        wt[k] = __ldg(reinterpret_cast<const float4*>(&Wp1[(2 * HH + k) * HH + j0]));
    float4 c0 = __ldg(reinterpret_cast<const float4*>(bp1) + p);
    float4 w2 = __ldg(reinterpret_cast<const float4*>(wp2) + p);
    float bias2 = __ldg(bp2);

    float res[EPT];
#pragma unroll
    for (int t = 0; t < EPT; t++) {
        long e = e0 + t;
        int s = __ldg(&ei[e]);
        int d = __ldg(&ei[EE + e]);
        float eav = (p < FE) ? __ldg(&eattr[e * FE + p]) : 0.0f;

        float4 av = unpack_h4(__ldg(reinterpret_cast<const uint2*>(&g_a[(long)s * HH]) + p));
        float4 bv = unpack_h4(__ldg(reinterpret_cast<const uint2*>(&g_b[(long)d * HH]) + p));

        float4 c = c0;
#pragma unroll
        for (int k = 0; k < FE; k++) {
            float ek = __shfl_sync(0xffffffffu, eav, k, 16);
            c.x = fmaf(ek, wt[k].x, c.x);
            c.y = fmaf(ek, wt[k].y, c.y);
            c.z = fmaf(ek, wt[k].z, c.z);
            c.w = fmaf(ek, wt[k].w, c.w);
        }

        float4 z;
        z.x = fmaxf(av.x + bv.x + c.x, 0.0f);
        z.y = fmaxf(av.y + bv.y + c.y, 0.0f);
        z.z = fmaxf(av.z + bv.z + c.z, 0.0f);
        z.w = fmaxf(av.w + bv.w + c.w, 0.0f);

        float part = z.x * w2.x + z.y * w2.y + z.z * w2.z + z.w * w2.w;
#pragma unroll
        for (int off = 8; off >= 1; off >>= 1)
            part += __shfl_down_sync(0xffffffffu, part, off, 16);

        res[t] = part + bias2;
    }
    if (p == 0)
        *reinterpret_cast<float4*>(&out[e0]) =
            make_float4(res[0], res[1], res[2], res[3]);
}

// ---------------- host launcher ----------------------------------------------
extern "C" void kernel_launch(void* const* d_in, const int* in_sizes, int n_in,
                              void* d_out, int out_size) {
    const float* x     = (const float*)d_in[0];
    const float* eattr = (const float*)d_in[1];
    const float* We    = (const float*)d_in[2];
    const float* be    = (const float*)d_in[3];
    const float* Wc1   = (const float*)d_in[4];
    const float* bc1   = (const float*)d_in[5];
    const float* Wc2   = (const float*)d_in[6];
    const float* bc2   = (const float*)d_in[7];
    const float* Wp1   = (const float*)d_in[8];
    const float* bp1   = (const float*)d_in[9];
    const float* wp2   = (const float*)d_in[10];
    const float* bp2   = (const float*)d_in[11];
    const int*   ei    = (const int*)d_in[12];
    float* out = (float*)d_out;

    // CSR build prologue
    k_zero<<<(NN + 255) / 256, 256>>>();
    k_deg<<<(EE + 255) / 256, 256>>>(ei);
    k_scanA<<<NB_SCAN, 256>>>();
    k_scanC<<<NB_SCAN, 256>>>();

    int ngrid = NN / NPB;          // 3125
    int ggrid = NN / 16;           // 6250

    // fork: k_fill runs concurrently with k_embed
    cudaStream_t s2;
    cudaStreamCreate(&s2);
    cudaEvent_t evFork, evJoin;
    cudaEventCreateWithFlags(&evFork, cudaEventDisableTiming);
    cudaEventCreateWithFlags(&evJoin, cudaEventDisableTiming);

    cudaEventRecord(evFork, 0);
    cudaStreamWaitEvent(s2, evFork, 0);
    k_fill<<<(EE + 255) / 256, 256, 0, s2>>>(ei);
    cudaEventRecord(evJoin, s2);

    k_embed<<<ngrid, 128>>>(x, We, be, Wc1);

    cudaStreamWaitEvent(0, evJoin, 0);

    k_gather<<<ggrid, 256>>>();
    k_mid<<<ngrid, 128>>>(bc1, Wc2);
    k_gather<<<ggrid, 256>>>();
    k_node_final<<<ngrid, 128>>>(bc2, Wp1);

    k_edge_out<<<EE / (16 * EPT), 256>>>(ei, eattr, Wp1, bp1, wp2, bp2, out);

    cudaEventDestroy(evFork);
    cudaEventDestroy(evJoin);
    cudaStreamDestroy(s2);
}

// round 11
// speedup vs baseline: 1.5827x; 1.0817x over previous
#include <cuda_runtime.h>
#include <cuda_bf16.h>
#include <cuda_fp16.h>
#include <mma.h>
#include <stdint.h>

using namespace nvcuda;

#define NN 100000
#define EE 1600000
#define FN 32
#define FE 8
#define HH 64
#define NB_SCAN 391   // ceil(NN/256)

// ---------------- scratch (device globals) ------------------------------------
__device__ __half g_g[NN * HH];   // fp16: g' = (h@W) * dinv
__device__ float  g_acc[NN * HH]; // fp32 aggregation target
__device__ __half g_a[NN * HH];   // fp16: h2 @ W_p1[0:64]
__device__ __half g_b[NN * HH];   // fp16: h2 @ W_p1[64:128]
__device__ float  g_dinv[NN];
__device__ int    g_degi[NN];
__device__ int    g_off[NN];
__device__ int    g_offtmp[NN];
__device__ int    g_cur[NN];
__device__ int    g_bsum[512];
__device__ int    g_csr[EE];

// ---------------- degree / norm / CSR build -----------------------------------
__global__ void k_zero() {
    int n = blockIdx.x * blockDim.x + threadIdx.x;
    if (n < NN) g_degi[n] = 0;
}

__global__ void k_deg(const int* __restrict__ ei) {
    int e = blockIdx.x * blockDim.x + threadIdx.x;
    if (e < EE) atomicAdd(&g_degi[__ldg(&ei[EE + e])], 1);
}

__global__ void k_scanA() {
    __shared__ int sm[256];
    int t = threadIdx.x;
    int idx = blockIdx.x * 256 + t;
    int v = (idx < NN) ? g_degi[idx] : 0;
    sm[t] = v;
    __syncthreads();
#pragma unroll
    for (int o = 1; o < 256; o <<= 1) {
        int x = (t >= o) ? sm[t - o] : 0;
        __syncthreads();
        sm[t] += x;
        __syncthreads();
    }
    if (idx < NN) g_offtmp[idx] = sm[t] - v;
    if (t == 255) g_bsum[blockIdx.x] = sm[255];
}

__global__ void k_scanC() {
    __shared__ int sm[256];
    int t = threadIdx.x;
    int bid = blockIdx.x;
    int v = 0;
    if (t < bid) v += g_bsum[t];
    if (t + 256 < bid) v += g_bsum[t + 256];
    sm[t] = v;
    __syncthreads();
#pragma unroll
    for (int o = 128; o > 0; o >>= 1) {
        if (t < o) sm[t] += sm[t + o];
        __syncthreads();
    }
    int bbase = sm[0];
    int idx = bid * 256 + t;
    if (idx < NN) {
        int o = g_offtmp[idx] + bbase;
        g_off[idx] = o;
        g_cur[idx] = o;
        g_dinv[idx] = rsqrtf((float)(g_degi[idx] + 1));
    }
}

__global__ void k_fill(const int* __restrict__ ei) {
    int e = blockIdx.x * blockDim.x + threadIdx.x;
    if (e < EE) {
        int d = __ldg(&ei[EE + e]);
        int pos = atomicAdd(&g_cur[d], 1);
        g_csr[pos] = __ldg(&ei[e]);
    }
}

// ================== node GEMM kernels: 256 threads, 32 nodes/block, HMMA =====
// 8 warps; output tiled 16x16 per warp; fp16 in, fp32 accumulate.

#define LDH 72    // fp16 ldm for 64-wide tiles (pad 64->72, 144B rows, 16B aligned)
#define LDX 40    // fp16 ldm for 32-wide x tile
#define LDC 72    // fp32 ldm for 64-wide C buffer
#define LDW 136   // fp16 ldm for 128-wide combined Wp1 tile
#define LDC2 136  // fp32 ldm for 128-wide C buffer

// ---------------- K1: h0 = relu(x@We+be); g1' = (h0@Wc1)*dinv ----------------
__global__ __launch_bounds__(256) void k_embed(const float* __restrict__ x,
                                               const float* __restrict__ We,
                                               const float* __restrict__ be,
                                               const float* __restrict__ Wc1) {
    const int tid = threadIdx.x;
    const int warp = tid >> 5;
    const int base = blockIdx.x * 32;

    __shared__ __align__(16) __half xh[32 * LDX];
    __shared__ __align__(16) __half weh[FN * LDH];
    __shared__ __align__(16) __half wch[HH * LDH];
    __shared__ __align__(16) __half hh[32 * LDH];
    __shared__ __align__(16) float  cbuf[32 * LDC];

    for (int i = tid; i < 32 * FN; i += 256)
        xh[(i >> 5) * LDX + (i & 31)] = __float2half(x[(long)base * FN + i]);
    for (int i = tid; i < FN * HH; i += 256)
        weh[(i >> 6) * LDH + (i & 63)] = __float2half(We[i]);
    for (int i = tid; i < HH * HH; i += 256)
        wch[(i >> 6) * LDH + (i & 63)] = __float2half(Wc1[i]);
    __syncthreads();

    const int wm = warp >> 2;      // 0..1
    const int wn = warp & 3;       // 0..3

    // stage 1: C = X @ We   (K=32)
    {
        wmma::fragment<wmma::accumulator, 16, 16, 16, float> cf;
        wmma::fill_fragment(cf, 0.0f);
#pragma unroll
        for (int kk = 0; kk < FN / 16; kk++) {
            wmma::fragment<wmma::matrix_a, 16, 16, 16, __half, wmma::row_major> af;
            wmma::fragment<wmma::matrix_b, 16, 16, 16, __half, wmma::row_major> bf;
            wmma::load_matrix_sync(af, xh + wm * 16 * LDX + kk * 16, LDX);
            wmma::load_matrix_sync(bf, weh + kk * 16 * LDH + wn * 16, LDH);
            wmma::mma_sync(cf, af, bf, cf);
        }
        wmma::store_matrix_sync(cbuf + wm * 16 * LDC + wn * 16, cf, LDC,
                                wmma::mem_row_major);
    }
    __syncthreads();

    // bias + relu -> hh fp16
    for (int i = tid; i < 32 * HH; i += 256) {
        int r = i >> 6, c = i & 63;
        hh[r * LDH + c] = __float2half(fmaxf(cbuf[r * LDC + c] + __ldg(&be[c]), 0.f));
    }
    __syncthreads();

    // stage 2: C = H @ Wc1  (K=64)
    {
        wmma::fragment<wmma::accumulator, 16, 16, 16, float> cf;
        wmma::fill_fragment(cf, 0.0f);
#pragma unroll
        for (int kk = 0; kk < HH / 16; kk++) {
            wmma::fragment<wmma::matrix_a, 16, 16, 16, __half, wmma::row_major> af;
            wmma::fragment<wmma::matrix_b, 16, 16, 16, __half, wmma::row_major> bf;
            wmma::load_matrix_sync(af, hh + wm * 16 * LDH + kk * 16, LDH);
            wmma::load_matrix_sync(bf, wch + kk * 16 * LDH + wn * 16, LDH);
            wmma::mma_sync(cf, af, bf, cf);
        }
        wmma::store_matrix_sync(cbuf + wm * 16 * LDC + wn * 16, cf, LDC,
                                wmma::mem_row_major);
    }
    __syncthreads();

    // scale by dinv, pack fp16 to g_g
    for (int i = tid; i < 32 * (HH / 2); i += 256) {
        int r = i >> 5, c2 = (i & 31) * 2;
        float di = g_dinv[base + r];
        __half2 hv = __floats2half2_rn(cbuf[r * LDC + c2] * di,
                                       cbuf[r * LDC + c2 + 1] * di);
        *reinterpret_cast<__half2*>(&g_g[(long)(base + r) * HH + c2]) = hv;
    }
}

// ---------------- gather-aggregate: acc[n] = g'[n] + sum_{s->n} g'[s] --------
__global__ __launch_bounds__(256) void k_gather() {
    const int tid = threadIdx.x;
    const int p = tid & 15;
    const int grp = tid >> 4;
    const int n = blockIdx.x * 16 + grp;
    const unsigned hm = 0xFFFFu << (tid & 16);

    uint2 selfraw = *reinterpret_cast<const uint2*>(&g_g[(long)n * HH + p * 4]);
    float2 lo = __half22float2(*reinterpret_cast<__half2*>(&selfraw.x));
    float2 hi = __half22float2(*reinterpret_cast<__half2*>(&selfraw.y));
    float4 acc = make_float4(lo.x, lo.y, hi.x, hi.y);

    const int beg = g_off[n];
    const int end = beg + g_degi[n];

    for (int b = beg; b < end; b += 16) {
        int rem = end - b;
        int cnt = rem < 16 ? rem : 16;
        int myi = (p < cnt) ? __ldg(&g_csr[b + p]) : 0;
        for (int k = 0; k < cnt; k++) {
            int s = __shfl_sync(hm, myi, k, 16);
            uint2 raw = __ldg(reinterpret_cast<const uint2*>(&g_g[(long)s * HH]) + p);
            float2 l2 = __half22float2(*reinterpret_cast<__half2*>(&raw.x));
            float2 h2 = __half22float2(*reinterpret_cast<__half2*>(&raw.y));
            acc.x += l2.x; acc.y += l2.y; acc.z += h2.x; acc.w += h2.y;
        }
    }
    *(float4*)&g_acc[(long)n * HH + p * 4] = acc;
}

// ---------------- K3: h1 = relu(acc*dinv + bc); g2' = (h1@Wc2)*dinv ----------
__global__ __launch_bounds__(256) void k_mid(const float* __restrict__ bc,
                                             const float* __restrict__ Wc) {
    const int tid = threadIdx.x;
    const int warp = tid >> 5;
    const int base = blockIdx.x * 32;

    __shared__ __align__(16) __half wch[HH * LDH];
    __shared__ __align__(16) __half hh[32 * LDH];
    __shared__ __align__(16) float  cbuf[32 * LDC];

    for (int i = tid; i < HH * HH; i += 256)
        wch[(i >> 6) * LDH + (i & 63)] = __float2half(Wc[i]);
    for (int i = tid; i < 32 * HH; i += 256) {
        int r = i >> 6, c = i & 63;
        float di = g_dinv[base + r];
        hh[r * LDH + c] = __float2half(
            fmaxf(fmaf(g_acc[(long)(base + r) * HH + c], di, __ldg(&bc[c])), 0.f));
    }
    __syncthreads();

    const int wm = warp >> 2;
    const int wn = warp & 3;
    {
        wmma::fragment<wmma::accumulator, 16, 16, 16, float> cf;
        wmma::fill_fragment(cf, 0.0f);
#pragma unroll
        for (int kk = 0; kk < HH / 16; kk++) {
            wmma::fragment<wmma::matrix_a, 16, 16, 16, __half, wmma::row_major> af;
            wmma::fragment<wmma::matrix_b, 16, 16, 16, __half, wmma::row_major> bf;
            wmma::load_matrix_sync(af, hh + wm * 16 * LDH + kk * 16, LDH);
            wmma::load_matrix_sync(bf, wch + kk * 16 * LDH + wn * 16, LDH);
            wmma::mma_sync(cf, af, bf, cf);
        }
        wmma::store_matrix_sync(cbuf + wm * 16 * LDC + wn * 16, cf, LDC,
                                wmma::mem_row_major);
    }
    __syncthreads();

    for (int i = tid; i < 32 * (HH / 2); i += 256) {
        int r = i >> 5, c2 = (i & 31) * 2;
        float di = g_dinv[base + r];
        __half2 hv = __floats2half2_rn(cbuf[r * LDC + c2] * di,
                                       cbuf[r * LDC + c2 + 1] * di);
        *reinterpret_cast<__half2*>(&g_g[(long)(base + r) * HH + c2]) = hv;
    }
}

// ---------------- K5: h2 = relu(acc*dinv + bc2); [a|b] = h2 @ Wp1' -----------
__global__ __launch_bounds__(256) void k_node_final(const float* __restrict__ bc2,
                                                    const float* __restrict__ Wp1) {
    const int tid = threadIdx.x;
    const int warp = tid >> 5;
    const int base = blockIdx.x * 32;

    __shared__ __align__(16) __half wab[HH * LDW];   // [64][128] combined
    __shared__ __align__(16) __half hh[32 * LDH];
    __shared__ __align__(16) float  cbuf[32 * LDC2]; // [32][128]

    // combined B': cols 0..63 <- Wp1 rows 0..63; cols 64..127 <- Wp1 rows 64..127
    for (int i = tid; i < HH * HH; i += 256) {
        int r = i >> 6, c = i & 63;
        wab[r * LDW + c] = __float2half(Wp1[r * HH + c]);
        wab[r * LDW + 64 + c] = __float2half(Wp1[(HH + r) * HH + c]);
    }
    for (int i = tid; i < 32 * HH; i += 256) {
        int r = i >> 6, c = i & 63;
        float di = g_dinv[base + r];
        hh[r * LDH + c] = __float2half(
            fmaxf(fmaf(g_acc[(long)(base + r) * HH + c], di, __ldg(&bc2[c])), 0.f));
    }
    __syncthreads();

    const int wm = warp >> 2;
    const int wn = warp & 3;
    {
        wmma::fragment<wmma::accumulator, 16, 16, 16, float> c0, c1;
        wmma::fill_fragment(c0, 0.0f);
        wmma::fill_fragment(c1, 0.0f);
#pragma unroll
        for (int kk = 0; kk < HH / 16; kk++) {
            wmma::fragment<wmma::matrix_a, 16, 16, 16, __half, wmma::row_major> af;
            wmma::fragment<wmma::matrix_b, 16, 16, 16, __half, wmma::row_major> b0, b1;
            wmma::load_matrix_sync(af, hh + wm * 16 * LDH + kk * 16, LDH);
            wmma::load_matrix_sync(b0, wab + kk * 16 * LDW + wn * 16, LDW);
            wmma::load_matrix_sync(b1, wab + kk * 16 * LDW + (wn + 4) * 16, LDW);
            wmma::mma_sync(c0, af, b0, c0);
            wmma::mma_sync(c1, af, b1, c1);
        }
        wmma::store_matrix_sync(cbuf + wm * 16 * LDC2 + wn * 16, c0, LDC2,
                                wmma::mem_row_major);
        wmma::store_matrix_sync(cbuf + wm * 16 * LDC2 + (wn + 4) * 16, c1, LDC2,
                                wmma::mem_row_major);
    }
    __syncthreads();

    for (int i = tid; i < 32 * 64; i += 256) {   // 64 half2 per row (128 cols)
        int r = i >> 6, c2 = (i & 63) * 2;
        __half2 hv = __floats2half2_rn(cbuf[r * LDC2 + c2], cbuf[r * LDC2 + c2 + 1]);
        if (c2 < 64)
            *reinterpret_cast<__half2*>(&g_a[(long)(base + r) * HH + c2]) = hv;
        else
            *reinterpret_cast<__half2*>(&g_b[(long)(base + r) * HH + (c2 - 64)]) = hv;
    }
}

// ---------------- K6: per-edge output, 4 edges per 16-thread group -----------
#define EPT 4
__global__ __launch_bounds__(256) void k_edge_out(const int* __restrict__ ei,
                           const float* __restrict__ eattr,
                           const float* __restrict__ Wp1,
                           const float* __restrict__ bp1,
                           const float* __restrict__ wp2,
                           const float* __restrict__ bp2,
                           float* __restrict__ out) {
    const int tid = threadIdx.x;
    const int p = tid & 15;
    const int grp = tid >> 4;
    const int j0 = p * 4;
    long e0 = ((long)blockIdx.x * 16 + grp) * EPT;

    float4 wt[FE];
#pragma unroll
    for (int k = 0; k < FE; k++)
        wt[k] = __ldg(reinterpret_cast<const float4*>(&Wp1[(2 * HH + k) * HH + j0]));
    float4 c0 = __ldg(reinterpret_cast<const float4*>(bp1) + p);
    float4 w2 = __ldg(reinterpret_cast<const float4*>(wp2) + p);
    float bias2 = __ldg(bp2);

    float res[EPT];
#pragma unroll
    for (int t = 0; t < EPT; t++) {
        long e = e0 + t;
        int s = __ldg(&ei[e]);
        int d = __ldg(&ei[EE + e]);
        float eav = (p < FE) ? __ldg(&eattr[e * FE + p]) : 0.0f;

        uint2 ar = __ldg(reinterpret_cast<const uint2*>(&g_a[(long)s * HH]) + p);
        uint2 br = __ldg(reinterpret_cast<const uint2*>(&g_b[(long)d * HH]) + p);
        float2 al = __half22float2(*reinterpret_cast<__half2*>(&ar.x));
        float2 ah = __half22float2(*reinterpret_cast<__half2*>(&ar.y));
        float2 bl = __half22float2(*reinterpret_cast<__half2*>(&br.x));
        float2 bh = __half22float2(*reinterpret_cast<__half2*>(&br.y));

        float4 c = c0;
#pragma unroll
        for (int k = 0; k < FE; k++) {
            float ek = __shfl_sync(0xffffffffu, eav, k, 16);
            c.x = fmaf(ek, wt[k].x, c.x);
            c.y = fmaf(ek, wt[k].y, c.y);
            c.z = fmaf(ek, wt[k].z, c.z);
            c.w = fmaf(ek, wt[k].w, c.w);
        }

        float4 z;
        z.x = fmaxf(al.x + bl.x + c.x, 0.0f);
        z.y = fmaxf(al.y + bl.y + c.y, 0.0f);
        z.z = fmaxf(ah.x + bh.x + c.z, 0.0f);
        z.w = fmaxf(ah.y + bh.y + c.w, 0.0f);

        float part = z.x * w2.x + z.y * w2.y + z.z * w2.z + z.w * w2.w;
#pragma unroll
        for (int off = 8; off >= 1; off >>= 1)
            part += __shfl_down_sync(0xffffffffu, part, off, 16);

        res[t] = part + bias2;
    }
    if (p == 0)
        *reinterpret_cast<float4*>(&out[e0]) =
            make_float4(res[0], res[1], res[2], res[3]);
}

// ---------------- host launcher ----------------------------------------------
extern "C" void kernel_launch(void* const* d_in, const int* in_sizes, int n_in,
                              void* d_out, int out_size) {
    const float* x     = (const float*)d_in[0];
    const float* eattr = (const float*)d_in[1];
    const float* We    = (const float*)d_in[2];
    const float* be    = (const float*)d_in[3];
    const float* Wc1   = (const float*)d_in[4];
    const float* bc1   = (const float*)d_in[5];
    const float* Wc2   = (const float*)d_in[6];
    const float* bc2   = (const float*)d_in[7];
    const float* Wp1   = (const float*)d_in[8];
    const float* bp1   = (const float*)d_in[9];
    const float* wp2   = (const float*)d_in[10];
    const float* bp2   = (const float*)d_in[11];
    const int*   ei    = (const int*)d_in[12];
    float* out = (float*)d_out;

    // CSR build prologue
    k_zero<<<(NN + 255) / 256, 256>>>();
    k_deg<<<(EE + 255) / 256, 256>>>(ei);
    k_scanA<<<NB_SCAN, 256>>>();
    k_scanC<<<NB_SCAN, 256>>>();

    int ngrid = NN / 32;           // 3125
    int ggrid = NN / 16;           // 6250

    // fork: k_fill runs concurrently with k_embed
    cudaStream_t s2;
    cudaStreamCreate(&s2);
    cudaEvent_t evFork, evJoin;
    cudaEventCreateWithFlags(&evFork, cudaEventDisableTiming);
    cudaEventCreateWithFlags(&evJoin, cudaEventDisableTiming);

    cudaEventRecord(evFork, 0);
    cudaStreamWaitEvent(s2, evFork, 0);
    k_fill<<<(EE + 255) / 256, 256, 0, s2>>>(ei);
    cudaEventRecord(evJoin, s2);

    k_embed<<<ngrid, 256>>>(x, We, be, Wc1);

    cudaStreamWaitEvent(0, evJoin, 0);

    k_gather<<<ggrid, 256>>>();
    k_mid<<<ngrid, 256>>>(bc1, Wc2);
    k_gather<<<ggrid, 256>>>();
    k_node_final<<<ngrid, 256>>>(bc2, Wp1);

    k_edge_out<<<EE / (16 * EPT), 256>>>(ei, eattr, Wp1, bp1, wp2, bp2, out);

    cudaEventDestroy(evFork);
    cudaEventDestroy(evJoin);
    cudaStreamDestroy(s2);
}